// round 6
// baseline (speedup 1.0000x reference)
#include <cuda_runtime.h>
#include <stdint.h>

#define Nn 2048
#define Ff 32
#define Ee 16
#define Kk 32

// Scratch (device globals — no allocation allowed)
__device__ float g_u[Nn * Ff];    // node_part + b_ne
__device__ float g_pre[Nn * Ff];  // (1+eps) * relu(nodes@W_n + b_n)

// Kernel A: per-node precompute. 65536 threads, one per (j,f).
__global__ void prep_kernel(const float* __restrict__ nodes,
                            const float* __restrict__ W_ne,
                            const float* __restrict__ b_ne,
                            const float* __restrict__ W_n,
                            const float* __restrict__ b_n,
                            const float* __restrict__ eps) {
    int t = blockIdx.x * blockDim.x + threadIdx.x;  // 0..N*F-1
    int j = t >> 5;
    int f = t & 31;
    const float* nrow = nodes + j * Ff;
    float s1 = 0.f, s2 = 0.f;
#pragma unroll
    for (int c = 0; c < Ff; c++) {
        float nv = nrow[c];
        s1 = fmaf(nv, W_ne[c * Ff + f], s1);  // node part of W_ne (rows [0,F))
        s2 = fmaf(nv, W_n[c * Ff + f], s2);
    }
    g_u[t] = s1 + b_ne[f];
    g_pre[t] = (1.0f + eps[0]) * fmaxf(s2 + b_n[f], 0.f);
}

// Fused kernel: one block per row i.
//   1. adj scan: coalesced read + fused adj->out copy + warp-ballot compaction
//      of nonzero (j, a) pairs into shared memory.
//   2. sparse msg: each warp walks its compacted list, 2 nonzeros per
//      iteration -> ~10 independent loads in flight (vs 4 serial before).
//   3. epilogue: block reduce + 32x32 FC + relu (warp 0).
//   4. bulk copy of edges row (128 KB) LAST, so every block ends with pure
//      streaming work and DRAM stays saturated across block boundaries.
__global__ __launch_bounds__(256) void fused_kernel(
    const float* __restrict__ adj,
    const float* __restrict__ edges,
    const float* __restrict__ W_ne,
    const float* __restrict__ W_net,
    const float* __restrict__ b_net,
    float* __restrict__ out_adj,
    float* __restrict__ out_y,
    float* __restrict__ out_edges) {
    int i = blockIdx.x;
    int t = threadIdx.x;
    int lane = t & 31;
    int w = t >> 5;  // warp 0..7

    __shared__ uint16_t sj[8][256];  // compacted neighbor indices per warp
    __shared__ float sa[8][256];     // corresponding adj values
    __shared__ float smsg[8][33];

    const float* adjrow = adj + (size_t)i * Nn;
    float* oadj = out_adj + (size_t)i * Nn;
    const float* erow = edges + (size_t)i * Nn * Ee;
    const float4* erow4 = reinterpret_cast<const float4*>(erow);

    // ---- Phase 1: adj scan + copy + compaction ----
    // Warp w owns j in {w*32 + c*256 + lane : c in [0,8)} (same partition &
    // order as previous rounds -> identical summation order).
    int cnt = 0;
#pragma unroll
    for (int c = 0; c < 8; c++) {
        int jb = w * 32 + c * 256;
        float a = adjrow[jb + lane];
        oadj[jb + lane] = a;  // fused adj pass-through copy
        unsigned mask = __ballot_sync(0xffffffffu, a != 0.f);
        int pos = cnt + __popc(mask & ((1u << lane) - 1u));
        if (a != 0.f) {
            sj[w][pos] = (uint16_t)(jb + lane);
            sa[w][pos] = a;
        }
        cnt += __popc(mask);
    }
    __syncwarp();

    // ---- Phase 2: sparse message, 2-way unrolled for MLP ----
    float we[Ee];
#pragma unroll
    for (int e = 0; e < Ee; e++) we[e] = W_ne[(Ff + e) * Ff + lane];

    float msg = 0.f;
    int idx = 0;
    for (; idx + 2 <= cnt; idx += 2) {
        int j0 = sj[w][idx];
        int j1 = sj[w][idx + 1];
        float a0 = sa[w][idx];
        float a1 = sa[w][idx + 1];
        const float4* p0 = erow4 + (size_t)j0 * 4;
        const float4* p1 = erow4 + (size_t)j1 * 4;
        float4 x0 = p0[0], x1 = p0[1], x2 = p0[2], x3 = p0[3];
        float4 y0 = p1[0], y1 = p1[1], y2 = p1[2], y3 = p1[3];
        float u0 = g_u[j0 * Ff + lane];
        float u1 = g_u[j1 * Ff + lane];

        float s0 = x0.x * we[0];
        s0 = fmaf(x0.y, we[1], s0);
        s0 = fmaf(x0.z, we[2], s0);
        s0 = fmaf(x0.w, we[3], s0);
        s0 = fmaf(x1.x, we[4], s0);
        s0 = fmaf(x1.y, we[5], s0);
        s0 = fmaf(x1.z, we[6], s0);
        s0 = fmaf(x1.w, we[7], s0);
        s0 = fmaf(x2.x, we[8], s0);
        s0 = fmaf(x2.y, we[9], s0);
        s0 = fmaf(x2.z, we[10], s0);
        s0 = fmaf(x2.w, we[11], s0);
        s0 = fmaf(x3.x, we[12], s0);
        s0 = fmaf(x3.y, we[13], s0);
        s0 = fmaf(x3.z, we[14], s0);
        s0 = fmaf(x3.w, we[15], s0);

        float s1 = y0.x * we[0];
        s1 = fmaf(y0.y, we[1], s1);
        s1 = fmaf(y0.z, we[2], s1);
        s1 = fmaf(y0.w, we[3], s1);
        s1 = fmaf(y1.x, we[4], s1);
        s1 = fmaf(y1.y, we[5], s1);
        s1 = fmaf(y1.z, we[6], s1);
        s1 = fmaf(y1.w, we[7], s1);
        s1 = fmaf(y2.x, we[8], s1);
        s1 = fmaf(y2.y, we[9], s1);
        s1 = fmaf(y2.z, we[10], s1);
        s1 = fmaf(y2.w, we[11], s1);
        s1 = fmaf(y3.x, we[12], s1);
        s1 = fmaf(y3.y, we[13], s1);
        s1 = fmaf(y3.z, we[14], s1);
        s1 = fmaf(y3.w, we[15], s1);

        msg = fmaf(a0, fmaxf(s0 + u0, 0.f), msg);
        msg = fmaf(a1, fmaxf(s1 + u1, 0.f), msg);
    }
    if (idx < cnt) {
        int j0 = sj[w][idx];
        float a0 = sa[w][idx];
        const float4* p0 = erow4 + (size_t)j0 * 4;
        float4 x0 = p0[0], x1 = p0[1], x2 = p0[2], x3 = p0[3];
        float u0 = g_u[j0 * Ff + lane];
        float s0 = x0.x * we[0];
        s0 = fmaf(x0.y, we[1], s0);
        s0 = fmaf(x0.z, we[2], s0);
        s0 = fmaf(x0.w, we[3], s0);
        s0 = fmaf(x1.x, we[4], s0);
        s0 = fmaf(x1.y, we[5], s0);
        s0 = fmaf(x1.z, we[6], s0);
        s0 = fmaf(x1.w, we[7], s0);
        s0 = fmaf(x2.x, we[8], s0);
        s0 = fmaf(x2.y, we[9], s0);
        s0 = fmaf(x2.z, we[10], s0);
        s0 = fmaf(x2.w, we[11], s0);
        s0 = fmaf(x3.x, we[12], s0);
        s0 = fmaf(x3.y, we[13], s0);
        s0 = fmaf(x3.z, we[14], s0);
        s0 = fmaf(x3.w, we[15], s0);
        msg = fmaf(a0, fmaxf(s0 + u0, 0.f), msg);
    }

    smsg[w][lane] = msg;
    __syncthreads();

    // ---- Phase 3: epilogue (warp 0) ----
    if (w == 0) {
        float m = 0.f;
#pragma unroll
        for (int k = 0; k < 8; k++) m += smsg[k][lane];
        float p = g_pre[i * Ff + lane] + m;  // (1+eps)*node_term + msg
        float acc = b_net[lane];
#pragma unroll
        for (int f = 0; f < Ff; f++)
            acc = fmaf(__shfl_sync(0xffffffffu, p, f), W_net[f * Kk + lane],
                       acc);
        out_y[(size_t)i * Kk + lane] = fmaxf(acc, 0.f);
    }

    // ---- Phase 4: bulk copy of this row's edge features (streaming tail) ----
    float4* oe4 = reinterpret_cast<float4*>(out_edges + (size_t)i * Nn * Ee);
#pragma unroll
    for (int r = 0; r < 4; r++) {
        float4 v0, v1, v2, v3, v4, v5, v6, v7;
        int base = t + r * 8 * 256;
        v0 = erow4[base + 0 * 256];
        v1 = erow4[base + 1 * 256];
        v2 = erow4[base + 2 * 256];
        v3 = erow4[base + 3 * 256];
        v4 = erow4[base + 4 * 256];
        v5 = erow4[base + 5 * 256];
        v6 = erow4[base + 6 * 256];
        v7 = erow4[base + 7 * 256];
        oe4[base + 0 * 256] = v0;
        oe4[base + 1 * 256] = v1;
        oe4[base + 2 * 256] = v2;
        oe4[base + 3 * 256] = v3;
        oe4[base + 4 * 256] = v4;
        oe4[base + 5 * 256] = v5;
        oe4[base + 6 * 256] = v6;
        oe4[base + 7 * 256] = v7;
    }
}

extern "C" void kernel_launch(void* const* d_in, const int* in_sizes, int n_in,
                              void* d_out, int out_size) {
    const float* adj = (const float*)d_in[0];
    const float* nodes = (const float*)d_in[1];
    const float* edges = (const float*)d_in[2];
    const float* W_ne = (const float*)d_in[3];
    const float* b_ne = (const float*)d_in[4];
    const float* W_n = (const float*)d_in[5];
    const float* b_n = (const float*)d_in[6];
    const float* W_net = (const float*)d_in[7];
    const float* b_net = (const float*)d_in[8];
    const float* eps = (const float*)d_in[9];

    float* out = (float*)d_out;
    float* out_adj = out;                                       // [N,N]
    float* out_y = out + (size_t)Nn * Nn;                       // [N,K]
    float* out_edges = out + (size_t)Nn * Nn + (size_t)Nn * Kk; // [N,N,E]

    prep_kernel<<<(Nn * Ff) / 256, 256>>>(nodes, W_ne, b_ne, W_n, b_n, eps);
    fused_kernel<<<Nn, 256>>>(adj, edges, W_ne, W_net, b_net, out_adj, out_y,
                              out_edges);
}